// round 2
// baseline (speedup 1.0000x reference)
#include <cuda_runtime.h>
#include <cuda_bf16.h>
#include <cstdint>

// ---------------- problem constants ----------------
#define B_    16
#define CIN   512
#define COUT  512
#define HS    36
#define WS    36
#define KK    3
#define HO    38           // conv output spatial (36 + 2*2 - 3 + 1)
#define WO    38
#define MTOT  (HO*WO)      // 1444 spatial positions per sample
#define WDIM  512
#define MDIM  64
#define TAPS  12
#define HOUT  36
#define WOUT  36

// ---------------- scratch (device globals; no allocation allowed) ----------------
__device__ float g_wt[9 * CIN * COUT];          // wn transposed: [tap][cin][cout], tf32-rounded
__device__ float g_q [COUT * CIN];              // Q[co][cin] = sum_tap wn^2
__device__ float g_sn[B_ * CIN];                // normalized styles
__device__ float g_scale[B_ * COUT];            // d * input_gain
__device__ float g_bmod [B_ * COUT];            // modulated bias
__device__ float g_y [B_ * COUT * MTOT];        // conv output (pre scale/bias)

// ---------------- kernel 1: weight prep ----------------
// per cout: wnorm = rsqrt(mean(w^2)); write wt[tap][cin][co] = rna_tf32(w*wnorm); Q[co][cin]
__global__ __launch_bounds__(256) void prep_kernel(const float* __restrict__ weight)
{
    int co = blockIdx.x;
    int tid = threadIdx.x;
    __shared__ float red[256];
    const float* wrow = weight + co * (CIN * 9);
    float s = 0.f;
    for (int i = tid; i < CIN * 9; i += 256) { float v = wrow[i]; s += v * v; }
    red[tid] = s; __syncthreads();
    for (int st = 128; st > 0; st >>= 1) { if (tid < st) red[tid] += red[tid + st]; __syncthreads(); }
    float wnorm = rsqrtf(red[0] / (float)(CIN * 9));
    for (int cin = tid; cin < CIN; cin += 256) {
        float q = 0.f;
        #pragma unroll
        for (int tap = 0; tap < 9; ++tap) {
            float wv = wrow[cin * 9 + tap] * wnorm;
            q += wv * wv;
            unsigned t; asm("cvt.rna.tf32.f32 %0, %1;" : "=r"(t) : "f"(wv));
            g_wt[(tap * CIN + cin) * COUT + co] = __uint_as_float(t);
        }
        g_q[co * CIN + cin] = q;
    }
}

// ---------------- kernel 2: styles / sn / modulated bias ----------------
__global__ __launch_bounds__(512) void style_kernel(
    const float* __restrict__ w, const float* __restrict__ msg,
    const float* __restrict__ aw, const float* __restrict__ ab,
    const float* __restrict__ bias, const float* __restrict__ msw,
    const float* __restrict__ mbw)
{
    int b = blockIdx.x;
    int tid = threadIdx.x;   // 512: cin index (also cout for bias)
    __shared__ float red[512];
    __shared__ float wS[WDIM];
    __shared__ float mS[MDIM];
    wS[tid] = w[b * WDIM + tid];
    if (tid < MDIM) mS[tid] = msg[b * MDIM + tid];
    __syncthreads();

    float s = ab[tid];
    const float* arow = aw + tid * WDIM;
    #pragma unroll 4
    for (int j = 0; j < WDIM; ++j) s += wS[j] * arow[j];
    float ms = 0.f;
    #pragma unroll
    for (int j = 0; j < MDIM; ++j) ms += mS[j] * msw[j * CIN + tid];
    s += 0.01f * ms;

    red[tid] = s * s; __syncthreads();
    for (int st = 256; st > 0; st >>= 1) { if (tid < st) red[tid] += red[tid + st]; __syncthreads(); }
    float rs = rsqrtf(red[0] / (float)CIN);
    g_sn[b * CIN + tid] = s * rs;

    float mb = 0.f;
    #pragma unroll
    for (int j = 0; j < MDIM; ++j) mb += mS[j] * mbw[j * COUT + tid];
    g_bmod[b * COUT + tid] = bias[tid] + 0.01f * mb;
}

// ---------------- kernel 3: demod scale ----------------
// scale[b][co] = rsqrt( sum_cin sn^2 * Q[co][cin] + 1e-8 ) * rsqrt(magnitude_ema)
__global__ __launch_bounds__(128) void demod_kernel(const float* __restrict__ magema)
{
    int b  = blockIdx.y;
    int co = blockIdx.x * 128 + threadIdx.x;
    __shared__ float sn2[CIN];
    for (int i = threadIdx.x; i < CIN; i += 128) { float v = g_sn[b * CIN + i]; sn2[i] = v * v; }
    __syncthreads();
    const float* q = g_q + co * CIN;
    float acc = 0.f;
    #pragma unroll 4
    for (int j = 0; j < CIN; ++j) acc += sn2[j] * q[j];
    g_scale[b * COUT + co] = rsqrtf(acc + 1e-8f) * rsqrtf(magema[0]);
}

// ---------------- kernel 4: implicit-GEMM conv (tf32 mma.sync) ----------------
// y[b][co][m] = sum_{tap,cin} x[b][cin][ih][iw]*sn[b][cin] * wn[co][cin][tap]
#define BM 128
#define BN 128
#define BK 32
#define LDSH 136   // bank = (8k + m) % 32 -> conflict-free fragment loads

__global__ __launch_bounds__(256) void conv_kernel(const float* __restrict__ x)
{
    __shared__ float As[BK][LDSH];
    __shared__ float Bs[BK][LDSH];
    __shared__ float snS[CIN];

    int b  = blockIdx.z;
    int m0 = blockIdx.x * BM;
    int n0 = blockIdx.y * BN;
    int tid = threadIdx.x;

    for (int i = tid; i < CIN; i += 256) snS[i] = g_sn[b * CIN + i];

    // A-load mapping: each thread owns one m column, two base k rows
    int am  = tid & 127;
    int ak0 = tid >> 7;                 // 0 or 1, step 2
    int mg  = m0 + am;
    bool mvalid = (mg < MTOT);
    int oh = mg / WO, ow = mg % WO;

    // B-load mapping: float4, each thread owns 4 n, k rows step 8
    int bn  = (tid & 31) * 4;
    int bk0 = tid >> 5;                 // 0..7

    int warp = tid >> 5, lane = tid & 31;
    int wm = (warp & 1) * 64;           // warp covers 64 m x 32 n
    int wn = (warp >> 1) * 32;

    float acc[4][4][4];
    #pragma unroll
    for (int a = 0; a < 4; ++a)
        #pragma unroll
        for (int c = 0; c < 4; ++c)
            #pragma unroll
            for (int r = 0; r < 4; ++r) acc[a][c][r] = 0.f;

    const float* xb = x + (size_t)b * CIN * HS * WS;

    for (int tap = 0; tap < 9; ++tap) {
        int kh = tap / 3, kw = tap % 3;
        int ih = oh + kh - 2, iw = ow + kw - 2;
        bool pvalid = mvalid && ((unsigned)ih < (unsigned)HS) && ((unsigned)iw < (unsigned)WS);
        const float* xptr = xb + ih * WS + iw;           // + cin*HS*WS
        const float* wtap = g_wt + tap * CIN * COUT;     // [cin][co]

        for (int cb = 0; cb < CIN; cb += BK) {
            __syncthreads();
            // ---- load A (x * sn, tf32-rounded) ----
            #pragma unroll
            for (int j = 0; j < 16; ++j) {
                int kl = ak0 + j * 2;
                int cin = cb + kl;
                float v = 0.f;
                if (pvalid) v = xptr[cin * (HS * WS)] * snS[cin];
                unsigned tv; asm("cvt.rna.tf32.f32 %0, %1;" : "=r"(tv) : "f"(v));
                As[kl][am] = __uint_as_float(tv);
            }
            // ---- load B (pre-rounded wt) ----
            #pragma unroll
            for (int j = 0; j < 4; ++j) {
                int kl = bk0 + j * 8;
                float4 v4 = *(const float4*)(wtap + (size_t)(cb + kl) * COUT + n0 + bn);
                *(float4*)(&Bs[kl][bn]) = v4;
            }
            __syncthreads();
            // ---- mma ----
            #pragma unroll
            for (int k8 = 0; k8 < BK; k8 += 8) {
                unsigned afr[4][4], bfr[4][2];
                int kc = k8 + (lane & 3);
                #pragma unroll
                for (int mt = 0; mt < 4; ++mt) {
                    int mr = wm + mt * 16 + (lane >> 2);
                    afr[mt][0] = __float_as_uint(As[kc    ][mr    ]);
                    afr[mt][1] = __float_as_uint(As[kc    ][mr + 8]);
                    afr[mt][2] = __float_as_uint(As[kc + 4][mr    ]);
                    afr[mt][3] = __float_as_uint(As[kc + 4][mr + 8]);
                }
                #pragma unroll
                for (int nt = 0; nt < 4; ++nt) {
                    int nc = wn + nt * 8 + (lane >> 2);
                    bfr[nt][0] = __float_as_uint(Bs[kc    ][nc]);
                    bfr[nt][1] = __float_as_uint(Bs[kc + 4][nc]);
                }
                #pragma unroll
                for (int mt = 0; mt < 4; ++mt)
                    #pragma unroll
                    for (int nt = 0; nt < 4; ++nt)
                        asm volatile(
                            "mma.sync.aligned.m16n8k8.row.col.f32.tf32.tf32.f32 "
                            "{%0,%1,%2,%3}, {%4,%5,%6,%7}, {%8,%9}, {%0,%1,%2,%3};"
                            : "+f"(acc[mt][nt][0]), "+f"(acc[mt][nt][1]),
                              "+f"(acc[mt][nt][2]), "+f"(acc[mt][nt][3])
                            : "r"(afr[mt][0]), "r"(afr[mt][1]), "r"(afr[mt][2]), "r"(afr[mt][3]),
                              "r"(bfr[nt][0]), "r"(bfr[nt][1]));
            }
        }
    }

    // ---- epilogue: y[b][co][m] ----
    float* yb = g_y + (size_t)b * COUT * MTOT;
    #pragma unroll
    for (int mt = 0; mt < 4; ++mt) {
        int mr = m0 + wm + mt * 16 + (lane >> 2);
        #pragma unroll
        for (int nt = 0; nt < 4; ++nt) {
            int nc = n0 + wn + nt * 8 + (lane & 3) * 2;
            if (mr < MTOT) {
                yb[(size_t)nc * MTOT + mr]       = acc[mt][nt][0];
                yb[(size_t)(nc + 1) * MTOT + mr] = acc[mt][nt][1];
            }
            if (mr + 8 < MTOT) {
                yb[(size_t)nc * MTOT + mr + 8]       = acc[mt][nt][2];
                yb[(size_t)(nc + 1) * MTOT + mr + 8] = acc[mt][nt][3];
            }
        }
    }
}

// ---------------- kernel 5: fused bias + up-FIR(x2) + lrelu/clamp + down-FIR(/2) ----------------
// One block per (b, cout) plane; everything in shared memory.
//  Y[38][40] -> U[82][40] (vert up) -> Z[82][84] (horiz up + gain*4 + lrelu + clamp)
//  -> T[36][84] (vert down, reuses U region) -> out[36][36]
__global__ __launch_bounds__(256) void filt_kernel(
    const float* __restrict__ fu_g, const float* __restrict__ fd_g,
    float* __restrict__ out)
{
    __shared__ float sm[11688];           // 46752 B
    float* U = sm;                        // 82*40 = 3280
    float* Y = sm + 3280;                 // 38*40 = 1520
    float* Z = sm + 4800;                 // 82*84 = 6888
    float* T = sm;                        // 36*84 = 3024 (reuse U)

    int plane = blockIdx.x;               // b*512 + co
    int tid = threadIdx.x;

    float fu[TAPS], fdr[TAPS];
    #pragma unroll
    for (int i = 0; i < TAPS; ++i) { fu[i] = fu_g[i]; fdr[i] = fd_g[TAPS - 1 - i]; }

    float sc = g_scale[plane];
    float bv = g_bmod[plane];
    const float* yp = g_y + (size_t)plane * MTOT;

    for (int i = tid; i < MTOT; i += 256) {
        int r = i / WO, c = i % WO;
        Y[r * 40 + c] = yp[i] * sc + bv;
    }
    __syncthreads();

    // vertical upsample: U[n][w], n in [0,82), z[n] = sum_i f[n+2-2i]*y[i]
    for (int i = tid; i < 82 * 38; i += 256) {
        int n = i / 38, wc = i % 38;
        float a = 0.f;
        int j0 = n & 1;
        #pragma unroll
        for (int jj = 0; jj < 6; ++jj) {
            int j = j0 + 2 * jj;
            int iy = (n + 2 - j) >> 1;
            if ((unsigned)iy < 38u) a += fu[j] * Y[iy * 40 + wc];
        }
        U[n * 40 + wc] = a;
    }
    __syncthreads();

    // horizontal upsample + gain + lrelu + clamp: Z[n][m]
    for (int i = tid; i < 82 * 82; i += 256) {
        int n = i / 82, m = i % 82;
        float a = 0.f;
        int j0 = m & 1;
        #pragma unroll
        for (int jj = 0; jj < 6; ++jj) {
            int j = j0 + 2 * jj;
            int iy = (m + 2 - j) >> 1;
            if ((unsigned)iy < 38u) a += fu[j] * U[n * 40 + iy];
        }
        a *= 4.0f;
        a = (a >= 0.f ? a : 0.2f * a) * 1.4142135623730951f;
        a = fminf(fmaxf(a, -256.f), 256.f);
        Z[n * 84 + m] = a;
    }
    __syncthreads();

    // vertical down: T[r][m] = sum_t fd[11-t]*Z[2r+t][m]
    for (int i = tid; i < 36 * 82; i += 256) {
        int r = i / 82, m = i % 82;
        float a = 0.f;
        #pragma unroll
        for (int t = 0; t < TAPS; ++t) a += fdr[t] * Z[(2 * r + t) * 84 + m];
        T[r * 84 + m] = a;
    }
    __syncthreads();

    // horizontal down + store
    float* op = out + (size_t)plane * (HOUT * WOUT);
    for (int i = tid; i < HOUT * WOUT; i += 256) {
        int r = i / WOUT, c = i % WOUT;
        float a = 0.f;
        #pragma unroll
        for (int t = 0; t < TAPS; ++t) a += fdr[t] * T[r * 84 + 2 * c + t];
        op[i] = a;
    }
}

// ---------------- launch ----------------
extern "C" void kernel_launch(void* const* d_in, const int* in_sizes, int n_in,
                              void* d_out, int out_size)
{
    const float* x      = (const float*)d_in[0];
    const float* w      = (const float*)d_in[1];
    const float* msg    = (const float*)d_in[2];
    const float* aw     = (const float*)d_in[3];
    const float* ab     = (const float*)d_in[4];
    const float* weight = (const float*)d_in[5];
    const float* bias   = (const float*)d_in[6];
    const float* msw    = (const float*)d_in[7];
    const float* mbw    = (const float*)d_in[8];
    const float* fu     = (const float*)d_in[9];
    const float* fd     = (const float*)d_in[10];
    const float* mag    = (const float*)d_in[11];
    float* outp = (float*)d_out;

    prep_kernel <<<COUT, 256>>>(weight);
    style_kernel<<<B_, 512>>>(w, msg, aw, ab, bias, msw, mbw);
    demod_kernel<<<dim3(COUT / 128, B_), 128>>>(mag);
    conv_kernel <<<dim3((MTOT + BM - 1) / BM, COUT / BN, B_), 256>>>(x);
    filt_kernel <<<B_ * COUT, 256>>>(fu, fd, outp);
}

// round 4
// speedup vs baseline: 1.0469x; 1.0469x over previous
#include <cuda_runtime.h>
#include <cuda_bf16.h>
#include <cstdint>

// ---------------- problem constants ----------------
#define B_    16
#define CIN   512
#define COUT  512
#define HS    36
#define WS    36
#define HO    38
#define WO    38
#define MTOT  (HO*WO)      // 1444
#define WDIM  512
#define MDIM  64
#define TAPS  12
#define HOUT  36
#define WOUT  36
#define KTOT  4608         // 9 * 512
#define HW    (HS*WS)      // 1296

// ---------------- scratch ----------------
__device__ float g_wt[9 * CIN * COUT];          // B matrix: [k][cout], k = tap*512+cin, tf32-rounded
__device__ float g_q [COUT * CIN];
__device__ float g_sn[B_ * CIN];
__device__ float g_xs[B_ * CIN * HW];           // x * sn, tf32-rounded
__device__ float g_scale[B_ * COUT];
__device__ float g_bmod [B_ * COUT];
__device__ float g_y [B_ * COUT * MTOT];        // conv output (scale+bias applied)

// ---------------- cp.async helpers ----------------
__device__ __forceinline__ uint32_t smem_u32(const void* p) {
    uint32_t a;
    asm("{ .reg .u64 t; cvta.to.shared.u64 t, %1; cvt.u32.u64 %0, t; }" : "=r"(a) : "l"(p));
    return a;
}
__device__ __forceinline__ void cp32(uint32_t dst, const void* src, uint32_t sz) {
    asm volatile("cp.async.ca.shared.global [%0], [%1], 4, %2;" :: "r"(dst), "l"(src), "r"(sz));
}
__device__ __forceinline__ void cp128(uint32_t dst, const void* src) {
    asm volatile("cp.async.cg.shared.global [%0], [%1], 16;" :: "r"(dst), "l"(src));
}
#define CP_COMMIT() asm volatile("cp.async.commit_group;" ::: "memory")
#define CP_WAIT1()  asm volatile("cp.async.wait_group 1;" ::: "memory")
#define CP_WAIT0()  asm volatile("cp.async.wait_group 0;" ::: "memory")

// ---------------- kernel 1: weight prep ----------------
__global__ __launch_bounds__(256) void prep_kernel(const float* __restrict__ weight)
{
    int co = blockIdx.x;
    int tid = threadIdx.x;
    __shared__ float red[256];
    const float* wrow = weight + co * (CIN * 9);
    float s = 0.f;
    for (int i = tid; i < CIN * 9; i += 256) { float v = wrow[i]; s += v * v; }
    red[tid] = s; __syncthreads();
    for (int st = 128; st > 0; st >>= 1) { if (tid < st) red[tid] += red[tid + st]; __syncthreads(); }
    float wnorm = rsqrtf(red[0] / (float)(CIN * 9));
    for (int cin = tid; cin < CIN; cin += 256) {
        float q = 0.f;
        #pragma unroll
        for (int tap = 0; tap < 9; ++tap) {
            float wv = wrow[cin * 9 + tap] * wnorm;
            q += wv * wv;
            unsigned t; asm("cvt.rna.tf32.f32 %0, %1;" : "=r"(t) : "f"(wv));
            g_wt[(size_t)(tap * CIN + cin) * COUT + co] = __uint_as_float(t);
        }
        g_q[co * CIN + cin] = q;
    }
}

// ---------------- kernel 2: styles ----------------
__global__ __launch_bounds__(512) void style_kernel(
    const float* __restrict__ w, const float* __restrict__ msg,
    const float* __restrict__ aw, const float* __restrict__ ab,
    const float* __restrict__ bias, const float* __restrict__ msw,
    const float* __restrict__ mbw)
{
    int b = blockIdx.x;
    int tid = threadIdx.x;
    __shared__ float red[512];
    __shared__ float wS[WDIM];
    __shared__ float mS[MDIM];
    wS[tid] = w[b * WDIM + tid];
    if (tid < MDIM) mS[tid] = msg[b * MDIM + tid];
    __syncthreads();

    float s = ab[tid];
    const float* arow = aw + tid * WDIM;
    #pragma unroll 4
    for (int j = 0; j < WDIM; ++j) s += wS[j] * arow[j];
    float ms = 0.f;
    #pragma unroll
    for (int j = 0; j < MDIM; ++j) ms += mS[j] * msw[j * CIN + tid];
    s += 0.01f * ms;

    red[tid] = s * s; __syncthreads();
    for (int st = 256; st > 0; st >>= 1) { if (tid < st) red[tid] += red[tid + st]; __syncthreads(); }
    float rs = rsqrtf(red[0] / (float)CIN);
    g_sn[b * CIN + tid] = s * rs;

    float mb = 0.f;
    #pragma unroll
    for (int j = 0; j < MDIM; ++j) mb += mS[j] * mbw[j * COUT + tid];
    g_bmod[b * COUT + tid] = bias[tid] + 0.01f * mb;
}

// ---------------- kernel 2b: xs = tf32(x * sn) ----------------
__global__ __launch_bounds__(256) void xs_kernel(const float* __restrict__ x)
{
    int idx = blockIdx.x * 256 + threadIdx.x;
    if (idx >= B_ * CIN * HW) return;
    int bc = idx / HW;
    float v = x[idx] * g_sn[bc];
    unsigned t; asm("cvt.rna.tf32.f32 %0, %1;" : "=r"(t) : "f"(v));
    g_xs[idx] = __uint_as_float(t);
}

// ---------------- kernel 3: demod ----------------
__global__ __launch_bounds__(128) void demod_kernel(const float* __restrict__ magema)
{
    int b  = blockIdx.y;
    int co = blockIdx.x * 128 + threadIdx.x;
    __shared__ float sn2[CIN];
    for (int i = threadIdx.x; i < CIN; i += 128) { float v = g_sn[b * CIN + i]; sn2[i] = v * v; }
    __syncthreads();
    const float* q = g_q + co * CIN;
    float acc = 0.f;
    #pragma unroll 4
    for (int j = 0; j < CIN; ++j) acc += sn2[j] * q[j];
    g_scale[b * COUT + co] = rsqrtf(acc + 1e-8f) * rsqrtf(magema[0]);
}

// ---------------- kernel 4: pipelined implicit-GEMM conv (tf32 mma.sync + cp.async) ----------------
#define BM 128
#define BN 128
#define BK 32
#define LDSH 136                 // float pitch; bank = (8k+m)%32 conflict-free
#define STAGE_B (BK * LDSH * 4)  // 17408 bytes per operand per stage
#define STAGE_AB (2 * STAGE_B)   // 34816
#define NSTAGE 3
#define SM_TILES (NSTAGE * STAGE_AB)   // 104448
#define CONV_SMEM (SM_TILES + 1024)    // + scale/bias

__global__ __launch_bounds__(256, 2) void conv3_kernel()
{
    extern __shared__ char dsm[];
    int tid  = threadIdx.x;
    int warp = tid >> 5, lane = tid & 31;

    int m0 = blockIdx.x * BM;
    int n0 = blockIdx.y * BN;
    int b  = blockIdx.z;

    uint32_t smemA[NSTAGE], smemB[NSTAGE];
    #pragma unroll
    for (int i = 0; i < NSTAGE; ++i) {
        smemA[i] = smem_u32(dsm + i * STAGE_AB);
        smemB[i] = smem_u32(dsm + i * STAGE_AB + STAGE_B);
    }
    float* scS = (float*)(dsm + SM_TILES);
    float* bvS = (float*)(dsm + SM_TILES + 512);

    if (tid < 128) {
        scS[tid] = g_scale[b * COUT + n0 + tid];
        bvS[tid] = g_bmod [b * COUT + n0 + tid];
    }

    // A-fill mapping: thread = (mloc 0..127, khalf 0..1); fills 16 k rows
    int mloc  = tid & 127;
    int khalf = tid >> 7;
    int mg = m0 + mloc;
    bool mval = (mg < MTOT);
    int oh = mg / WO, ow = mg % WO;
    const float* xsb = g_xs + (size_t)b * CIN * HW;

    // MMA warp mapping (identical to the R2-passing kernel)
    int wm = (warp & 1) * 64;
    int wn = (warp >> 1) * 32;

    float acc[4][4][4];
    #pragma unroll
    for (int a = 0; a < 4; ++a)
        #pragma unroll
        for (int c = 0; c < 4; ++c)
            #pragma unroll
            for (int r = 0; r < 4; ++r) acc[a][c][r] = 0.f;

    // ---- stage filler (144 stages: tap = s>>4, cin-block = s&15) ----
    auto fill_stage = [&](int s) {
        int buf = s % NSTAGE;
        int tap = s >> 4;
        int kh = tap / 3, kw = tap % 3;
        int ih = oh + kh - 2, iw = ow + kw - 2;
        bool pv = mval && ((unsigned)ih < (unsigned)HS) && ((unsigned)iw < (unsigned)WS);
        const float* xrow = pv ? (xsb + ih * WS + iw) : xsb;
        uint32_t sz = pv ? 4u : 0u;
        int c0 = (s & 15) * 32 + khalf * 16;
        uint32_t adst = smemA[buf] + (uint32_t)(khalf * 16) * (LDSH * 4) + (uint32_t)mloc * 4;
        const float* asrc = xrow + (size_t)c0 * HW;
        #pragma unroll
        for (int j = 0; j < 16; ++j)
            cp32(adst + j * (LDSH * 4), asrc + (size_t)j * HW, sz);
        // B: rows of 128 contiguous floats (g_wt is [k][cout])
        #pragma unroll
        for (int j = 0; j < 4; ++j) {
            int fi = tid + j * 256;         // 0..1023
            int kl = fi >> 5, ch = fi & 31; // 32 rows x 32 chunks(16B)
            cp128(smemB[buf] + (uint32_t)kl * (LDSH * 4) + (uint32_t)ch * 16,
                  g_wt + (size_t)(s * 32 + kl) * COUT + n0 + ch * 4);
        }
        CP_COMMIT();
    };

    // prologue: stages 0,1 in flight
    fill_stage(0);
    fill_stage(1);

    for (int s = 0; s < 144; ++s) {
        int buf = s % NSTAGE;
        if (s < 143) { CP_WAIT1(); } else { CP_WAIT0(); }
        __syncthreads();
        if (s + 2 < 144) fill_stage(s + 2);

        float (*As)[LDSH] = (float(*)[LDSH])(dsm + buf * STAGE_AB);
        float (*Bs)[LDSH] = (float(*)[LDSH])(dsm + buf * STAGE_AB + STAGE_B);

        #pragma unroll
        for (int k8 = 0; k8 < BK; k8 += 8) {
            unsigned afr[4][4], bfr[4][2];
            int kc = k8 + (lane & 3);
            #pragma unroll
            for (int mt = 0; mt < 4; ++mt) {
                int mr = wm + mt * 16 + (lane >> 2);
                afr[mt][0] = __float_as_uint(As[kc    ][mr    ]);
                afr[mt][1] = __float_as_uint(As[kc    ][mr + 8]);
                afr[mt][2] = __float_as_uint(As[kc + 4][mr    ]);
                afr[mt][3] = __float_as_uint(As[kc + 4][mr + 8]);
            }
            #pragma unroll
            for (int nt = 0; nt < 4; ++nt) {
                int nc = wn + nt * 8 + (lane >> 2);
                bfr[nt][0] = __float_as_uint(Bs[kc    ][nc]);
                bfr[nt][1] = __float_as_uint(Bs[kc + 4][nc]);
            }
            #pragma unroll
            for (int mt = 0; mt < 4; ++mt)
                #pragma unroll
                for (int nt = 0; nt < 4; ++nt)
                    asm volatile(
                        "mma.sync.aligned.m16n8k8.row.col.f32.tf32.tf32.f32 "
                        "{%0,%1,%2,%3}, {%4,%5,%6,%7}, {%8,%9}, {%0,%1,%2,%3};"
                        : "+f"(acc[mt][nt][0]), "+f"(acc[mt][nt][1]),
                          "+f"(acc[mt][nt][2]), "+f"(acc[mt][nt][3])
                        : "r"(afr[mt][0]), "r"(afr[mt][1]), "r"(afr[mt][2]), "r"(afr[mt][3]),
                          "r"(bfr[nt][0]), "r"(bfr[nt][1]));
        }
    }

    // ---- epilogue: scale + bias, write g_y ----
    float* yb = g_y + (size_t)b * COUT * MTOT;
    #pragma unroll
    for (int mt = 0; mt < 4; ++mt) {
        int mr = m0 + wm + mt * 16 + (lane >> 2);
        #pragma unroll
        for (int nt = 0; nt < 4; ++nt) {
            int ncl = wn + nt * 8 + (lane & 3) * 2;
            int nc  = n0 + ncl;
            float s0 = scS[ncl],     b0v = bvS[ncl];
            float s1 = scS[ncl + 1], b1v = bvS[ncl + 1];
            if (mr < MTOT) {
                yb[(size_t)nc * MTOT + mr]       = acc[mt][nt][0] * s0 + b0v;
                yb[(size_t)(nc + 1) * MTOT + mr] = acc[mt][nt][1] * s1 + b1v;
            }
            if (mr + 8 < MTOT) {
                yb[(size_t)nc * MTOT + mr + 8]       = acc[mt][nt][2] * s0 + b0v;
                yb[(size_t)(nc + 1) * MTOT + mr + 8] = acc[mt][nt][3] * s1 + b1v;
            }
        }
    }
}

// ---------------- kernel 5: fused filter chain ----------------
__global__ __launch_bounds__(256) void filt_kernel(
    const float* __restrict__ fu_g, const float* __restrict__ fd_g,
    float* __restrict__ out)
{
    __shared__ float sm[11688];
    float* U = sm;                        // 82*40
    float* Y = sm + 3280;                 // 38*40
    float* Z = sm + 4800;                 // 82*84
    float* T = sm;                        // 36*84 (reuse U)

    int plane = blockIdx.x;
    int tid = threadIdx.x;

    float fu[TAPS], fdr[TAPS];
    #pragma unroll
    for (int i = 0; i < TAPS; ++i) { fu[i] = fu_g[i]; fdr[i] = fd_g[TAPS - 1 - i]; }

    const float* yp = g_y + (size_t)plane * MTOT;
    for (int i = tid; i < MTOT; i += 256) {
        int r = i / WO, c = i % WO;
        Y[r * 40 + c] = yp[i];
    }
    __syncthreads();

    for (int i = tid; i < 82 * 38; i += 256) {
        int n = i / 38, wc = i % 38;
        float a = 0.f;
        int j0 = n & 1;
        #pragma unroll
        for (int jj = 0; jj < 6; ++jj) {
            int j = j0 + 2 * jj;
            int iy = (n + 2 - j) >> 1;
            if ((unsigned)iy < 38u) a += fu[j] * Y[iy * 40 + wc];
        }
        U[n * 40 + wc] = a;
    }
    __syncthreads();

    for (int i = tid; i < 82 * 82; i += 256) {
        int n = i / 82, m = i % 82;
        float a = 0.f;
        int j0 = m & 1;
        #pragma unroll
        for (int jj = 0; jj < 6; ++jj) {
            int j = j0 + 2 * jj;
            int iy = (m + 2 - j) >> 1;
            if ((unsigned)iy < 38u) a += fu[j] * U[n * 40 + iy];
        }
        a *= 4.0f;
        a = (a >= 0.f ? a : 0.2f * a) * 1.4142135623730951f;
        a = fminf(fmaxf(a, -256.f), 256.f);
        Z[n * 84 + m] = a;
    }
    __syncthreads();

    for (int i = tid; i < 36 * 82; i += 256) {
        int r = i / 82, m = i % 82;
        float a = 0.f;
        #pragma unroll
        for (int t = 0; t < TAPS; ++t) a += fdr[t] * Z[(2 * r + t) * 84 + m];
        T[r * 84 + m] = a;
    }
    __syncthreads();

    float* op = out + (size_t)plane * (HOUT * WOUT);
    for (int i = tid; i < HOUT * WOUT; i += 256) {
        int r = i / WOUT, c = i % WOUT;
        float a = 0.f;
        #pragma unroll
        for (int t = 0; t < TAPS; ++t) a += fdr[t] * T[r * 84 + 2 * c + t];
        op[i] = a;
    }
}

// ---------------- launch ----------------
extern "C" void kernel_launch(void* const* d_in, const int* in_sizes, int n_in,
                              void* d_out, int out_size)
{
    const float* x      = (const float*)d_in[0];
    const float* w      = (const float*)d_in[1];
    const float* msg    = (const float*)d_in[2];
    const float* aw     = (const float*)d_in[3];
    const float* ab     = (const float*)d_in[4];
    const float* weight = (const float*)d_in[5];
    const float* bias   = (const float*)d_in[6];
    const float* msw    = (const float*)d_in[7];
    const float* mbw    = (const float*)d_in[8];
    const float* fu     = (const float*)d_in[9];
    const float* fd     = (const float*)d_in[10];
    const float* mag    = (const float*)d_in[11];
    float* outp = (float*)d_out;

    cudaFuncSetAttribute(conv3_kernel, cudaFuncAttributeMaxDynamicSharedMemorySize, CONV_SMEM);

    prep_kernel <<<COUT, 256>>>(weight);
    style_kernel<<<B_, 512>>>(w, msg, aw, ab, bias, msw, mbw);
    xs_kernel   <<<(B_ * CIN * HW + 255) / 256, 256>>>(x);
    demod_kernel<<<dim3(COUT / 128, B_), 128>>>(mag);
    conv3_kernel<<<dim3((MTOT + BM - 1) / BM, COUT / BN, B_), 256, CONV_SMEM>>>();
    filt_kernel <<<B_ * COUT, 256>>>(fu, fd, outp);
}

// round 5
// speedup vs baseline: 1.1445x; 1.0932x over previous
#include <cuda_runtime.h>
#include <cuda_bf16.h>
#include <cstdint>

// ---------------- problem constants ----------------
#define B_    16
#define CIN   512
#define COUT  512
#define HS    36
#define WS    36
#define HO    38
#define WO    38
#define MTOT  (HO*WO)      // 1444
#define WDIM  512
#define MDIM  64
#define TAPS  12
#define HOUT  36
#define WOUT  36
#define KTOT  4608         // 9 * 512
#define HW    (HS*WS)      // 1296

// ---------------- scratch ----------------
// g_wt: fragment-blocked B. 144 ktiles x 4 ntiles, each 4096 floats (16 KB):
//   off = (((k8*4 + wnq)*4 + nt)*32 + lane)*2 + r2
//   where k_local=k%32: k8=k_local>>3, r2=(k_local>>2)&1, lane=(n%8)*4+(k_local&3),
//         nt=(n>>3)&3, wnq=(n>>5)&3   (n = co within 128-wide ntile)
__device__ float g_wt[144 * 4 * 4096];
__device__ float g_q [COUT * CIN];
__device__ float g_sn[B_ * CIN];
__device__ float g_xs[B_ * CIN * HW];           // x * sn, tf32-rounded
__device__ float g_scale[B_ * COUT];
__device__ float g_bmod [B_ * COUT];
__device__ float g_y [B_ * COUT * MTOT];

// ---------------- cp.async helpers ----------------
__device__ __forceinline__ uint32_t smem_u32(const void* p) {
    uint32_t a;
    asm("{ .reg .u64 t; cvta.to.shared.u64 t, %1; cvt.u32.u64 %0, t; }" : "=r"(a) : "l"(p));
    return a;
}
__device__ __forceinline__ void cp32(uint32_t dst, const void* src, uint32_t sz) {
    asm volatile("cp.async.ca.shared.global [%0], [%1], 4, %2;" :: "r"(dst), "l"(src), "r"(sz));
}
__device__ __forceinline__ void cp128(uint32_t dst, const void* src) {
    asm volatile("cp.async.cg.shared.global [%0], [%1], 16;" :: "r"(dst), "l"(src));
}
#define CP_COMMIT() asm volatile("cp.async.commit_group;" ::: "memory")
#define CP_WAIT1()  asm volatile("cp.async.wait_group 1;" ::: "memory")
#define CP_WAIT0()  asm volatile("cp.async.wait_group 0;" ::: "memory")

// ---------------- kernel 1: weight prep (writes fragment-blocked B) ----------------
__global__ __launch_bounds__(256) void prep_kernel(const float* __restrict__ weight)
{
    int co = blockIdx.x;
    int tid = threadIdx.x;
    __shared__ float red[256];
    const float* wrow = weight + co * (CIN * 9);
    float s = 0.f;
    for (int i = tid; i < CIN * 9; i += 256) { float v = wrow[i]; s += v * v; }
    red[tid] = s; __syncthreads();
    for (int st = 128; st > 0; st >>= 1) { if (tid < st) red[tid] += red[tid + st]; __syncthreads(); }
    float wnorm = rsqrtf(red[0] / (float)(CIN * 9));

    int ntile = co >> 7;
    int wnq   = (co >> 5) & 3;
    int nt    = (co >> 3) & 3;
    int lane_n = (co & 7) * 4;

    for (int cin = tid; cin < CIN; cin += 256) {
        float q = 0.f;
        #pragma unroll
        for (int tap = 0; tap < 9; ++tap) {
            float wv = wrow[cin * 9 + tap] * wnorm;
            q += wv * wv;
            unsigned t; asm("cvt.rna.tf32.f32 %0, %1;" : "=r"(t) : "f"(wv));
            int k = tap * CIN + cin;
            int s5 = k >> 5, kl = k & 31;
            int k8 = kl >> 3, r2 = (kl >> 2) & 1, lane = lane_n + (kl & 3);
            size_t off = (size_t)(s5 * 4 + ntile) * 4096
                       + (size_t)((((k8 * 4 + wnq) * 4 + nt) * 32 + lane) * 2 + r2);
            g_wt[off] = __uint_as_float(t);
        }
        g_q[co * CIN + cin] = q;
    }
}

// ---------------- kernel 2: styles ----------------
__global__ __launch_bounds__(512) void style_kernel(
    const float* __restrict__ w, const float* __restrict__ msg,
    const float* __restrict__ aw, const float* __restrict__ ab,
    const float* __restrict__ bias, const float* __restrict__ msw,
    const float* __restrict__ mbw)
{
    int b = blockIdx.x;
    int tid = threadIdx.x;
    __shared__ float red[512];
    __shared__ float wS[WDIM];
    __shared__ float mS[MDIM];
    wS[tid] = w[b * WDIM + tid];
    if (tid < MDIM) mS[tid] = msg[b * MDIM + tid];
    __syncthreads();

    float s = ab[tid];
    const float* arow = aw + tid * WDIM;
    #pragma unroll 4
    for (int j = 0; j < WDIM; ++j) s += wS[j] * arow[j];
    float ms = 0.f;
    #pragma unroll
    for (int j = 0; j < MDIM; ++j) ms += mS[j] * msw[j * CIN + tid];
    s += 0.01f * ms;

    red[tid] = s * s; __syncthreads();
    for (int st = 256; st > 0; st >>= 1) { if (tid < st) red[tid] += red[tid + st]; __syncthreads(); }
    float rs = rsqrtf(red[0] / (float)CIN);
    g_sn[b * CIN + tid] = s * rs;

    float mb = 0.f;
    #pragma unroll
    for (int j = 0; j < MDIM; ++j) mb += mS[j] * mbw[j * COUT + tid];
    g_bmod[b * COUT + tid] = bias[tid] + 0.01f * mb;
}

// ---------------- kernel 2b: xs = tf32(x * sn) ----------------
__global__ __launch_bounds__(256) void xs_kernel(const float* __restrict__ x)
{
    int idx = blockIdx.x * 256 + threadIdx.x;
    if (idx >= B_ * CIN * HW) return;
    int bc = idx / HW;
    float v = x[idx] * g_sn[bc];
    unsigned t; asm("cvt.rna.tf32.f32 %0, %1;" : "=r"(t) : "f"(v));
    g_xs[idx] = __uint_as_float(t);
}

// ---------------- kernel 3: demod (warp per (b,co)) ----------------
__global__ __launch_bounds__(256) void demod_kernel(const float* __restrict__ magema)
{
    int gw   = blockIdx.x * 8 + (threadIdx.x >> 5);   // 0..8191
    int lane = threadIdx.x & 31;
    int b  = gw >> 9;
    int co = gw & 511;
    const float4* q  = (const float4*)(g_q  + (size_t)co * CIN);
    const float4* sn = (const float4*)(g_sn + (size_t)b  * CIN);
    float acc = 0.f;
    #pragma unroll
    for (int j = 0; j < 4; ++j) {
        float4 qv = q [lane + j * 32];
        float4 sv = sn[lane + j * 32];
        acc += sv.x * sv.x * qv.x + sv.y * sv.y * qv.y
             + sv.z * sv.z * qv.z + sv.w * sv.w * qv.w;
    }
    #pragma unroll
    for (int o = 16; o > 0; o >>= 1) acc += __shfl_xor_sync(0xFFFFFFFF, acc, o);
    if (lane == 0)
        g_scale[gw] = rsqrtf(acc + 1e-8f) * rsqrtf(magema[0]);
}

// ---------------- kernel 4: pipelined implicit-GEMM conv ----------------
#define BM 128
#define BN 128
#define BK 32
#define LDSH 136                  // A pitch (floats); conflict-free
#define A_BYTES (BK * LDSH * 4)   // 17408
#define B_BYTES 16384             // fragment-blocked B tile
#define STAGE_AB (A_BYTES + B_BYTES)  // 33792
#define NSTAGE 3
#define SM_TILES (NSTAGE * STAGE_AB)  // 101376
#define CONV_SMEM (SM_TILES + 1024)

__global__ __launch_bounds__(256, 2) void conv3_kernel()
{
    extern __shared__ char dsm[];
    int tid  = threadIdx.x;
    int warp = tid >> 5, lane = tid & 31;

    int m0    = blockIdx.x * BM;
    int ntile = blockIdx.y;           // 0..3
    int n0    = ntile * BN;
    int b     = blockIdx.z;

    uint32_t smemA[NSTAGE], smemB[NSTAGE];
    #pragma unroll
    for (int i = 0; i < NSTAGE; ++i) {
        smemA[i] = smem_u32(dsm + i * STAGE_AB);
        smemB[i] = smem_u32(dsm + i * STAGE_AB + A_BYTES);
    }
    float* scS = (float*)(dsm + SM_TILES);
    float* bvS = (float*)(dsm + SM_TILES + 512);

    if (tid < 128) {
        scS[tid] = g_scale[b * COUT + n0 + tid];
        bvS[tid] = g_bmod [b * COUT + n0 + tid];
    }

    // A-fill mapping: thread = (mloc, khalf) fills 16 k-rows, one m column
    int mloc  = tid & 127;
    int khalf = tid >> 7;
    int mg = m0 + mloc;
    bool mval = (mg < MTOT);
    int oh = mg / WO, ow = mg % WO;
    const float* xsb = g_xs + (size_t)b * CIN * HW;

    int wm  = (warp & 1) * 64;
    int wnq = warp >> 1;              // 0..3 (32-col quad)

    float acc[4][4][4];
    #pragma unroll
    for (int a = 0; a < 4; ++a)
        #pragma unroll
        for (int c = 0; c < 4; ++c)
            #pragma unroll
            for (int r = 0; r < 4; ++r) acc[a][c][r] = 0.f;

    auto fill_stage = [&](int s) {
        int buf = s % NSTAGE;
        int tap = s >> 4;
        int kh = tap / 3, kw = tap % 3;
        int ih = oh + kh - 2, iw = ow + kw - 2;
        bool pv = mval && ((unsigned)ih < (unsigned)HS) && ((unsigned)iw < (unsigned)WS);
        const float* xrow = pv ? (xsb + ih * WS + iw) : xsb;
        uint32_t sz = pv ? 4u : 0u;
        int c0 = (s & 15) * 32 + khalf * 16;
        uint32_t adst = smemA[buf] + (uint32_t)(khalf * 16) * (LDSH * 4) + (uint32_t)mloc * 4;
        const float* asrc = xrow + (size_t)c0 * HW;
        #pragma unroll
        for (int j = 0; j < 16; ++j)
            cp32(adst + j * (LDSH * 4), asrc + (size_t)j * HW, sz);
        // B: linear 16 KB copy of the fragment-blocked tile
        const float* bsrc = g_wt + (size_t)(s * 4 + ntile) * 4096;
        #pragma unroll
        for (int j = 0; j < 4; ++j) {
            int chunk = tid + j * 256;          // 0..1023, 16B each
            cp128(smemB[buf] + (uint32_t)chunk * 16, bsrc + chunk * 4);
        }
        CP_COMMIT();
    };

    fill_stage(0);
    fill_stage(1);

    for (int s = 0; s < 144; ++s) {
        int buf = s % NSTAGE;
        if (s < 143) { CP_WAIT1(); } else { CP_WAIT0(); }
        __syncthreads();

        float (*As)[LDSH] = (float(*)[LDSH])(dsm + buf * STAGE_AB);
        const float* Bf = (const float*)(dsm + buf * STAGE_AB + A_BYTES);

        #pragma unroll
        for (int k8 = 0; k8 < 4; ++k8) {
            unsigned afr[4][4], bfr[4][2];
            int kc = k8 * 8 + (lane & 3);
            #pragma unroll
            for (int mt = 0; mt < 4; ++mt) {
                int mr = wm + mt * 16 + (lane >> 2);
                afr[mt][0] = __float_as_uint(As[kc    ][mr    ]);
                afr[mt][1] = __float_as_uint(As[kc    ][mr + 8]);
                afr[mt][2] = __float_as_uint(As[kc + 4][mr    ]);
                afr[mt][3] = __float_as_uint(As[kc + 4][mr + 8]);
            }
            #pragma unroll
            for (int nt = 0; nt < 4; ++nt) {
                float2 bv = *(const float2*)(Bf + (((k8 * 4 + wnq) * 4 + nt) * 32 + lane) * 2);
                bfr[nt][0] = __float_as_uint(bv.x);
                bfr[nt][1] = __float_as_uint(bv.y);
            }
            #pragma unroll
            for (int mt = 0; mt < 4; ++mt)
                #pragma unroll
                for (int nt = 0; nt < 4; ++nt)
                    asm volatile(
                        "mma.sync.aligned.m16n8k8.row.col.f32.tf32.tf32.f32 "
                        "{%0,%1,%2,%3}, {%4,%5,%6,%7}, {%8,%9}, {%0,%1,%2,%3};"
                        : "+f"(acc[mt][nt][0]), "+f"(acc[mt][nt][1]),
                          "+f"(acc[mt][nt][2]), "+f"(acc[mt][nt][3])
                        : "r"(afr[mt][0]), "r"(afr[mt][1]), "r"(afr[mt][2]), "r"(afr[mt][3]),
                          "r"(bfr[nt][0]), "r"(bfr[nt][1]));
        }

        if (s + 2 < 144) fill_stage(s + 2);   // after MMA: off the tensor critical path
    }

    // ---- epilogue: scale + bias, write g_y ----
    float* yb = g_y + (size_t)b * COUT * MTOT;
    int wn = wnq * 32;
    #pragma unroll
    for (int mt = 0; mt < 4; ++mt) {
        int mr = m0 + wm + mt * 16 + (lane >> 2);
        #pragma unroll
        for (int nt = 0; nt < 4; ++nt) {
            int ncl = wn + nt * 8 + (lane & 3) * 2;
            int nc  = n0 + ncl;
            float s0 = scS[ncl],     b0v = bvS[ncl];
            float s1 = scS[ncl + 1], b1v = bvS[ncl + 1];
            if (mr < MTOT) {
                yb[(size_t)nc * MTOT + mr]       = acc[mt][nt][0] * s0 + b0v;
                yb[(size_t)(nc + 1) * MTOT + mr] = acc[mt][nt][1] * s1 + b1v;
            }
            if (mr + 8 < MTOT) {
                yb[(size_t)nc * MTOT + mr + 8]       = acc[mt][nt][2] * s0 + b0v;
                yb[(size_t)(nc + 1) * MTOT + mr + 8] = acc[mt][nt][3] * s1 + b1v;
            }
        }
    }
}

// ---------------- kernel 5: fused filter chain ----------------
__global__ __launch_bounds__(256) void filt_kernel(
    const float* __restrict__ fu_g, const float* __restrict__ fd_g,
    float* __restrict__ out)
{
    __shared__ float sm[11688];
    float* U = sm;                        // 82*40
    float* Y = sm + 3280;                 // 38*40
    float* Z = sm + 4800;                 // 82*84
    float* T = sm;                        // 36*84 (reuse U)

    int plane = blockIdx.x;
    int tid = threadIdx.x;

    float fu[TAPS], fdr[TAPS];
    #pragma unroll
    for (int i = 0; i < TAPS; ++i) { fu[i] = fu_g[i]; fdr[i] = fd_g[TAPS - 1 - i]; }

    const float* yp = g_y + (size_t)plane * MTOT;
    for (int i = tid; i < MTOT; i += 256) {
        int r = i / WO, c = i % WO;
        Y[r * 40 + c] = yp[i];
    }
    __syncthreads();

    for (int i = tid; i < 82 * 38; i += 256) {
        int n = i / 38, wc = i % 38;
        float a = 0.f;
        int j0 = n & 1;
        #pragma unroll
        for (int jj = 0; jj < 6; ++jj) {
            int j = j0 + 2 * jj;
            int iy = (n + 2 - j) >> 1;
            if ((unsigned)iy < 38u) a += fu[j] * Y[iy * 40 + wc];
        }
        U[n * 40 + wc] = a;
    }
    __syncthreads();

    for (int i = tid; i < 82 * 82; i += 256) {
        int n = i / 82, m = i % 82;
        float a = 0.f;
        int j0 = m & 1;
        #pragma unroll
        for (int jj = 0; jj < 6; ++jj) {
            int j = j0 + 2 * jj;
            int iy = (m + 2 - j) >> 1;
            if ((unsigned)iy < 38u) a += fu[j] * U[n * 40 + iy];
        }
        a *= 4.0f;
        a = (a >= 0.f ? a : 0.2f * a) * 1.4142135623730951f;
        a = fminf(fmaxf(a, -256.f), 256.f);
        Z[n * 84 + m] = a;
    }
    __syncthreads();

    for (int i = tid; i < 36 * 82; i += 256) {
        int r = i / 82, m = i % 82;
        float a = 0.f;
        #pragma unroll
        for (int t = 0; t < TAPS; ++t) a += fdr[t] * Z[(2 * r + t) * 84 + m];
        T[r * 84 + m] = a;
    }
    __syncthreads();

    float* op = out + (size_t)plane * (HOUT * WOUT);
    for (int i = tid; i < HOUT * WOUT; i += 256) {
        int r = i / WOUT, c = i % WOUT;
        float a = 0.f;
        #pragma unroll
        for (int t = 0; t < TAPS; ++t) a += fdr[t] * T[r * 84 + 2 * c + t];
        op[i] = a;
    }
}

// ---------------- launch ----------------
extern "C" void kernel_launch(void* const* d_in, const int* in_sizes, int n_in,
                              void* d_out, int out_size)
{
    const float* x      = (const float*)d_in[0];
    const float* w      = (const float*)d_in[1];
    const float* msg    = (const float*)d_in[2];
    const float* aw     = (const float*)d_in[3];
    const float* ab     = (const float*)d_in[4];
    const float* weight = (const float*)d_in[5];
    const float* bias   = (const float*)d_in[6];
    const float* msw    = (const float*)d_in[7];
    const float* mbw    = (const float*)d_in[8];
    const float* fu     = (const float*)d_in[9];
    const float* fd     = (const float*)d_in[10];
    const float* mag    = (const float*)d_in[11];
    float* outp = (float*)d_out;

    cudaFuncSetAttribute(conv3_kernel, cudaFuncAttributeMaxDynamicSharedMemorySize, CONV_SMEM);

    prep_kernel <<<COUT, 256>>>(weight);
    style_kernel<<<B_, 512>>>(w, msg, aw, ab, bias, msw, mbw);
    xs_kernel   <<<(B_ * CIN * HW + 255) / 256, 256>>>(x);
    demod_kernel<<<1024, 256>>>(mag);
    conv3_kernel<<<dim3((MTOT + BM - 1) / BM, COUT / BN, B_), 256, CONV_SMEM>>>();
    filt_kernel <<<B_ * COUT, 256>>>(fu, fd, outp);
}